// round 1
// baseline (speedup 1.0000x reference)
#include <cuda_runtime.h>

// Problem constants
#define BB    16
#define CIN   3
#define HIMG  256
#define PSZ   16
#define HP    16      // patches per side
#define PPI   256     // patches per image
#define NTOK  4096    // total patches
#define NE    8
#define CCAP  640
#define NCOUT 8

// Scratch (device globals; no allocation allowed)
__device__ float g_gate_pos[PPI * NE];   // pos-feature + bias gate contribution per (patch-pos, expert)
__device__ int   g_eidx[NTOK];
__device__ float g_gate[NTOK];           // prob at argmax; zeroed by rank kernel if dropped
__device__ float g_psum[NE];             // sum of probs per expert (for aux)
__device__ int   g_cnt[NE];              // count per expert (for aux)
__device__ float g_feat[BB * 512];       // pooled features

// ---------------------------------------------------------------------------
// Kernel 1: init — block 0 computes gate_pos table + zeroes psum;
//           blocks 1..32 zero g_feat.
// ---------------------------------------------------------------------------
__global__ void init_kernel(const float* __restrict__ gate_w,
                            const float* __restrict__ gate_b) {
    int bid = blockIdx.x;
    int t = threadIdx.x;
    if (bid == 0) {
        if (t < NE) g_psum[t] = 0.f;
        int p = t;                 // 256 threads = 256 patch positions
        int r = p >> 4, c = p & 15;
        const float PI2 = 6.283185307179586f;
        float sgx = 0.f, s0x = 0.f, c0x = 0.f, s1x = 0.f, c1x = 0.f;
        for (int j = 0; j < 16; j++) {
            float gx = (float)(c * 16 + j) * (1.0f / 256.0f);
            sgx += gx;
            float a = PI2 * gx;
            s0x += sinf(a);        c0x += cosf(a);
            s1x += sinf(2.f * a);  c1x += cosf(2.f * a);
        }
        float sgy = 0.f, s0y = 0.f, c0y = 0.f, s1y = 0.f, c1y = 0.f;
        for (int i = 0; i < 16; i++) {
            float gy = (float)(r * 16 + i) * (1.0f / 256.0f);
            sgy += gy;
            float a = PI2 * gy;
            s0y += sinf(a);        c0y += cosf(a);
            s1y += sinf(2.f * a);  c1y += cosf(2.f * a);
        }
        float pcx = (c + 0.5f) / 16.f, pcy = (r + 0.5f) / 16.f;
        float S[20];
        S[0]  = 16.f * sgx;              S[1]  = 16.f * sgy;
        S[2]  = 256.f * pcx;             S[3]  = 256.f * pcy;
        S[4]  = 16.f * s0x;              S[5]  = 16.f * c0x;
        S[6]  = 16.f * s0y;              S[7]  = 16.f * c0y;
        S[8]  = 256.f * sinf(PI2 * pcx); S[9]  = 256.f * cosf(PI2 * pcx);
        S[10] = 256.f * sinf(PI2 * pcy); S[11] = 256.f * cosf(PI2 * pcy);
        S[12] = 16.f * s1x;              S[13] = 16.f * c1x;
        S[14] = 16.f * s1y;              S[15] = 16.f * c1y;
        S[16] = 256.f * sinf(2.f * PI2 * pcx); S[17] = 256.f * cosf(2.f * PI2 * pcx);
        S[18] = 256.f * sinf(2.f * PI2 * pcy); S[19] = 256.f * cosf(2.f * PI2 * pcy);
        #pragma unroll
        for (int e = 0; e < NE; e++) {
            float acc = 0.f;
            #pragma unroll
            for (int cc = 0; cc < 20; cc++)
                acc += S[cc] * gate_w[e * 23 + 3 + cc];
            g_gate_pos[p * NE + e] = acc * (1.f / 256.f) + gate_b[e];
        }
    } else {
        int idx = (bid - 1) * 256 + t;
        if (idx < BB * 512) g_feat[idx] = 0.f;
    }
}

// ---------------------------------------------------------------------------
// Kernel 2: gating — one warp per patch. Channel sums over 256 px,
// logits -> softmax -> argmax, prob accumulation for aux.
// ---------------------------------------------------------------------------
__global__ void __launch_bounds__(256) gate_kernel(const float* __restrict__ X,
                                                   const float* __restrict__ gate_w) {
    __shared__ float s_psum[NE];
    int t = threadIdx.x;
    if (t < NE) s_psum[t] = 0.f;
    __syncthreads();

    int warp = t >> 5, lane = t & 31;
    int n = blockIdx.x * 8 + warp;
    int b = n >> 8, p = n & 255;
    int r = p >> 4, c = p & 15;

    float s[3];
    #pragma unroll
    for (int ch = 0; ch < 3; ch++) {
        const float* base = X + ((size_t)(b * 3 + ch) * 256 + r * 16) * 256 + c * 16;
        float acc = 0.f;
        #pragma unroll
        for (int it = 0; it < 2; it++) {
            float4 v = *(const float4*)(base + (size_t)((lane >> 2) + it * 8) * 256 + (lane & 3) * 4);
            acc += v.x + v.y + v.z + v.w;
        }
        #pragma unroll
        for (int off = 16; off; off >>= 1)
            acc += __shfl_down_sync(0xffffffffu, acc, off);
        s[ch] = __shfl_sync(0xffffffffu, acc, 0);
    }

    float lg = -1e30f;
    if (lane < NE) {
        lg = (s[0] * gate_w[lane * 23 + 0] + s[1] * gate_w[lane * 23 + 1] +
              s[2] * gate_w[lane * 23 + 2]) * (1.f / 256.f)
             + g_gate_pos[p * NE + lane];
    }
    // max over the 8-lane group (xor offsets 1,2,4 stay within the group)
    float m = lg;
    #pragma unroll
    for (int off = 4; off; off >>= 1)
        m = fmaxf(m, __shfl_xor_sync(0xffffffffu, m, off));
    float pe = (lane < NE) ? expf(lg - m) : 0.f;
    float sum = pe;
    #pragma unroll
    for (int off = 4; off; off >>= 1)
        sum += __shfl_xor_sync(0xffffffffu, sum, off);
    if (lane < NE) {
        float prob = pe / sum;
        atomicAdd(&s_psum[lane], prob);
    }
    unsigned mask = __ballot_sync(0xffffffffu, lg == m) & 0xFFu;
    if (lane == 0) {
        g_eidx[n] = __ffs(mask) - 1;        // first tie wins (matches jnp.argmax)
        g_gate[n] = 1.0f / sum;             // prob at argmax = exp(0)/sum
    }
    __syncthreads();
    if (t < NE) atomicAdd(&g_psum[t], s_psum[t]);
}

// ---------------------------------------------------------------------------
// Kernel 3: ordered rank per expert (capacity drop). 8 warps, 1 block.
// Warp w scans all 4096 tokens via ballot; base = ordered prefix count.
// ---------------------------------------------------------------------------
__global__ void rank_kernel() {
    int w = threadIdx.x >> 5, lane = threadIdx.x & 31;
    int base = 0;
    for (int tt = 0; tt < NTOK / 32; tt++) {
        int idx = tt * 32 + lane;
        int e = g_eidx[idx];
        unsigned mask = __ballot_sync(0xffffffffu, e == w);
        if (e == w) {
            int rank = base + __popc(mask & ((1u << lane) - 1u));
            if (rank >= CCAP) g_gate[idx] = 0.f;   // dropped
        }
        base += __popc(mask);
    }
    if (lane == 0) g_cnt[w] = base;
}

// ---------------------------------------------------------------------------
// Kernel 4: per-patch 3x3 conv (SAME, zero-pad at patch edges) + ReLU +
// per-channel sum -> gated accumulate into pooled features.
// One block (256 threads) per patch; thread = pixel.
// ---------------------------------------------------------------------------
__global__ void __launch_bounds__(256) conv_kernel(const float* __restrict__ X,
                                                   const float* __restrict__ ew,
                                                   const float* __restrict__ eb) {
    __shared__ float sh_in[3][18][18];
    __shared__ float sh_w[216];
    __shared__ float sh_b[8];
    __shared__ float sh_ws[8][8];   // [warp][co]

    int n = blockIdx.x;
    float gate = g_gate[n];
    if (gate == 0.f) return;        // uniform across block (dropped patch -> zero contribution)
    int e = g_eidx[n];
    int t = threadIdx.x;
    int b = n >> 8, p = n & 255;
    int r = p >> 4, c = p & 15;

    if (t < 216) sh_w[t] = ew[e * 216 + t];
    if (t >= 224 && t < 232) sh_b[t - 224] = eb[e * 8 + (t - 224)];

    const float* Xb = X + (size_t)b * 3 * 65536 + (size_t)(r * 16) * 256 + c * 16;
    for (int idx = t; idx < 3 * 18 * 18; idx += 256) {
        int ci = idx / 324;
        int rem = idx - ci * 324;
        int ii = rem / 18, jj = rem - (rem / 18) * 18;
        float v = 0.f;
        if (ii >= 1 && ii <= 16 && jj >= 1 && jj <= 16)
            v = Xb[(size_t)ci * 65536 + (ii - 1) * 256 + (jj - 1)];
        sh_in[ci][ii][jj] = v;
    }
    __syncthreads();

    int i = t >> 4, j = t & 15;
    float in_reg[3][9];
    #pragma unroll
    for (int ci = 0; ci < 3; ci++)
        #pragma unroll
        for (int dy = 0; dy < 3; dy++)
            #pragma unroll
            for (int dx = 0; dx < 3; dx++)
                in_reg[ci][dy * 3 + dx] = sh_in[ci][i + dy][j + dx];

    float y[8];
    #pragma unroll
    for (int co = 0; co < 8; co++) {
        float acc = sh_b[co];
        #pragma unroll
        for (int ci = 0; ci < 3; ci++)
            #pragma unroll
            for (int k = 0; k < 9; k++)
                acc += sh_w[co * 27 + ci * 9 + k] * in_reg[ci][k];
        y[co] = fmaxf(acc, 0.f);
    }

    #pragma unroll
    for (int co = 0; co < 8; co++) {
        float v = y[co];
        #pragma unroll
        for (int off = 16; off; off >>= 1)
            v += __shfl_down_sync(0xffffffffu, v, off);
        if ((t & 31) == 0) sh_ws[t >> 5][co] = v;
    }
    __syncthreads();
    if (t < 8) {
        float tot = 0.f;
        #pragma unroll
        for (int w = 0; w < 8; w++) tot += sh_ws[w][t];
        int py = r >> 1, px = c >> 1;
        atomicAdd(&g_feat[b * 512 + t * 64 + py * 8 + px], tot * gate * (1.f / 1024.f));
    }
}

// ---------------------------------------------------------------------------
// Kernel 5: classifier GEMM [16,512]x[512,1000] + bias, plus aux loss.
// grid (8 j-tiles, 16 batch), 128 threads.
// ---------------------------------------------------------------------------
__global__ void __launch_bounds__(128) linear_kernel(const float* __restrict__ lw,
                                                     const float* __restrict__ lb,
                                                     float* __restrict__ out,
                                                     int out_size) {
    __shared__ float fs[512];
    int bx = blockIdx.x, by = blockIdx.y;
    int t = threadIdx.x;
    for (int k = t; k < 512; k += 128) fs[k] = g_feat[by * 512 + k];
    __syncthreads();

    int j = bx * 128 + t;
    if (j < 1000) {
        float acc = 0.f;
        #pragma unroll 8
        for (int k = 0; k < 512; k++)
            acc += fs[k] * lw[(size_t)k * 1000 + j];
        out[by * 1000 + j] = acc + lb[j];
    }
    if (bx == 0 && by == 0 && t == 0) {
        float aux = 0.f;
        #pragma unroll
        for (int e = 0; e < NE; e++) {
            float f = fminf((float)g_cnt[e], (float)CCAP) * (1.f / (float)NTOK);
            aux += f * (g_psum[e] * (1.f / (float)NTOK));
        }
        out[out_size - 1] = 8.f * aux;
    }
}

// ---------------------------------------------------------------------------
extern "C" void kernel_launch(void* const* d_in, const int* in_sizes, int n_in,
                              void* d_out, int out_size) {
    const float* X  = (const float*)d_in[0];
    const float* ew = (const float*)d_in[1];
    const float* eb = (const float*)d_in[2];
    const float* gw = (const float*)d_in[3];
    const float* gb = (const float*)d_in[4];
    const float* lw = (const float*)d_in[5];
    const float* lb = (const float*)d_in[6];
    float* out = (float*)d_out;

    init_kernel<<<33, 256>>>(gw, gb);
    gate_kernel<<<NTOK / 8, 256>>>(X, gw);
    rank_kernel<<<1, 256>>>();
    conv_kernel<<<NTOK, 256>>>(X, ew, eb);
    dim3 g(8, 16);
    linear_kernel<<<g, 128>>>(lw, lb, out, out_size);
}

// round 2
// speedup vs baseline: 1.0141x; 1.0141x over previous
#include <cuda_runtime.h>

// Problem constants
#define BB    16
#define CIN   3
#define HIMG  256
#define PSZ   16
#define HP    16      // patches per side
#define PPI   256     // patches per image
#define NTOK  4096    // total patches
#define NE    8
#define CCAP  640
#define NCOUT 8

// Scratch (device globals; no allocation allowed)
__device__ float g_gate_pos[PPI * NE];   // pos-feature + bias gate contribution per (patch-pos, expert)
__device__ int   g_eidx[NTOK];
__device__ float g_gate[NTOK];           // prob at argmax; zeroed by rank kernel if dropped
__device__ float g_psum[NE];             // sum of probs per expert (for aux)
__device__ int   g_cnt[NE];              // count per expert (for aux)
__device__ float g_feat[BB * 512];       // pooled features

// ---------------------------------------------------------------------------
// Kernel 1: init — block 0 computes gate_pos table + zeroes psum;
//           blocks 1..32 zero g_feat.
// ---------------------------------------------------------------------------
__global__ void init_kernel(const float* __restrict__ gate_w,
                            const float* __restrict__ gate_b) {
    int bid = blockIdx.x;
    int t = threadIdx.x;
    if (bid == 0) {
        if (t < NE) g_psum[t] = 0.f;
        int p = t;                 // 256 threads = 256 patch positions
        int r = p >> 4, c = p & 15;
        const float PI2 = 6.283185307179586f;
        float sgx = 0.f, s0x = 0.f, c0x = 0.f, s1x = 0.f, c1x = 0.f;
        for (int j = 0; j < 16; j++) {
            float gx = (float)(c * 16 + j) * (1.0f / 256.0f);
            sgx += gx;
            float a = PI2 * gx;
            s0x += sinf(a);        c0x += cosf(a);
            s1x += sinf(2.f * a);  c1x += cosf(2.f * a);
        }
        float sgy = 0.f, s0y = 0.f, c0y = 0.f, s1y = 0.f, c1y = 0.f;
        for (int i = 0; i < 16; i++) {
            float gy = (float)(r * 16 + i) * (1.0f / 256.0f);
            sgy += gy;
            float a = PI2 * gy;
            s0y += sinf(a);        c0y += cosf(a);
            s1y += sinf(2.f * a);  c1y += cosf(2.f * a);
        }
        float pcx = (c + 0.5f) / 16.f, pcy = (r + 0.5f) / 16.f;
        float S[20];
        S[0]  = 16.f * sgx;              S[1]  = 16.f * sgy;
        S[2]  = 256.f * pcx;             S[3]  = 256.f * pcy;
        S[4]  = 16.f * s0x;              S[5]  = 16.f * c0x;
        S[6]  = 16.f * s0y;              S[7]  = 16.f * c0y;
        S[8]  = 256.f * sinf(PI2 * pcx); S[9]  = 256.f * cosf(PI2 * pcx);
        S[10] = 256.f * sinf(PI2 * pcy); S[11] = 256.f * cosf(PI2 * pcy);
        S[12] = 16.f * s1x;              S[13] = 16.f * c1x;
        S[14] = 16.f * s1y;              S[15] = 16.f * c1y;
        S[16] = 256.f * sinf(2.f * PI2 * pcx); S[17] = 256.f * cosf(2.f * PI2 * pcx);
        S[18] = 256.f * sinf(2.f * PI2 * pcy); S[19] = 256.f * cosf(2.f * PI2 * pcy);
        #pragma unroll
        for (int e = 0; e < NE; e++) {
            float acc = 0.f;
            #pragma unroll
            for (int cc = 0; cc < 20; cc++)
                acc += S[cc] * gate_w[e * 23 + 3 + cc];
            g_gate_pos[p * NE + e] = acc * (1.f / 256.f) + gate_b[e];
        }
    } else {
        int idx = (bid - 1) * 256 + t;
        if (idx < BB * 512) g_feat[idx] = 0.f;
    }
}

// ---------------------------------------------------------------------------
// Kernel 2: gating — one warp per patch. Channel sums over 256 px,
// logits -> softmax -> argmax, prob accumulation for aux.
// ---------------------------------------------------------------------------
__global__ void __launch_bounds__(256) gate_kernel(const float* __restrict__ X,
                                                   const float* __restrict__ gate_w) {
    __shared__ float s_psum[NE];
    int t = threadIdx.x;
    if (t < NE) s_psum[t] = 0.f;
    __syncthreads();

    int warp = t >> 5, lane = t & 31;
    int n = blockIdx.x * 8 + warp;
    int b = n >> 8, p = n & 255;
    int r = p >> 4, c = p & 15;

    float s[3];
    #pragma unroll
    for (int ch = 0; ch < 3; ch++) {
        const float* base = X + ((size_t)(b * 3 + ch) * 256 + r * 16) * 256 + c * 16;
        float acc = 0.f;
        #pragma unroll
        for (int it = 0; it < 2; it++) {
            float4 v = *(const float4*)(base + (size_t)((lane >> 2) + it * 8) * 256 + (lane & 3) * 4);
            acc += v.x + v.y + v.z + v.w;
        }
        #pragma unroll
        for (int off = 16; off; off >>= 1)
            acc += __shfl_down_sync(0xffffffffu, acc, off);
        s[ch] = __shfl_sync(0xffffffffu, acc, 0);
    }

    float lg = -1e30f;
    if (lane < NE) {
        lg = (s[0] * gate_w[lane * 23 + 0] + s[1] * gate_w[lane * 23 + 1] +
              s[2] * gate_w[lane * 23 + 2]) * (1.f / 256.f)
             + g_gate_pos[p * NE + lane];
    }
    // max over the 8-lane group (xor offsets 1,2,4 stay within the group)
    float m = lg;
    #pragma unroll
    for (int off = 4; off; off >>= 1)
        m = fmaxf(m, __shfl_xor_sync(0xffffffffu, m, off));
    float pe = (lane < NE) ? expf(lg - m) : 0.f;
    float sum = pe;
    #pragma unroll
    for (int off = 4; off; off >>= 1)
        sum += __shfl_xor_sync(0xffffffffu, sum, off);
    if (lane < NE) {
        float prob = pe / sum;
        atomicAdd(&s_psum[lane], prob);
    }
    unsigned mask = __ballot_sync(0xffffffffu, lg == m) & 0xFFu;
    if (lane == 0) {
        g_eidx[n] = __ffs(mask) - 1;        // first tie wins (matches jnp.argmax)
        g_gate[n] = 1.0f / sum;             // prob at argmax = exp(0)/sum
    }
    __syncthreads();
    if (t < NE) atomicAdd(&g_psum[t], s_psum[t]);
}

// ---------------------------------------------------------------------------
// Kernel 3: ordered rank per expert (capacity drop). 8 warps, 1 block.
// Warp w scans all 4096 tokens via ballot; base = ordered prefix count.
// ---------------------------------------------------------------------------
__global__ void rank_kernel() {
    int w = threadIdx.x >> 5, lane = threadIdx.x & 31;
    int base = 0;
    for (int tt = 0; tt < NTOK / 32; tt++) {
        int idx = tt * 32 + lane;
        int e = g_eidx[idx];
        unsigned mask = __ballot_sync(0xffffffffu, e == w);
        if (e == w) {
            int rank = base + __popc(mask & ((1u << lane) - 1u));
            if (rank >= CCAP) g_gate[idx] = 0.f;   // dropped
        }
        base += __popc(mask);
    }
    if (lane == 0) g_cnt[w] = base;
}

// ---------------------------------------------------------------------------
// Kernel 4: per-patch 3x3 conv (SAME, zero-pad at patch edges) + ReLU +
// per-channel sum -> gated accumulate into pooled features.
// One block (256 threads) per patch; thread = pixel.
// ---------------------------------------------------------------------------
__global__ void __launch_bounds__(256) conv_kernel(const float* __restrict__ X,
                                                   const float* __restrict__ ew,
                                                   const float* __restrict__ eb) {
    __shared__ float sh_in[3][18][18];
    __shared__ float sh_w[216];
    __shared__ float sh_b[8];
    __shared__ float sh_ws[8][8];   // [warp][co]

    int n = blockIdx.x;
    float gate = g_gate[n];
    if (gate == 0.f) return;        // uniform across block (dropped patch -> zero contribution)
    int e = g_eidx[n];
    int t = threadIdx.x;
    int b = n >> 8, p = n & 255;
    int r = p >> 4, c = p & 15;

    if (t < 216) sh_w[t] = ew[e * 216 + t];
    if (t >= 224 && t < 232) sh_b[t - 224] = eb[e * 8 + (t - 224)];

    const float* Xb = X + (size_t)b * 3 * 65536 + (size_t)(r * 16) * 256 + c * 16;
    for (int idx = t; idx < 3 * 18 * 18; idx += 256) {
        int ci = idx / 324;
        int rem = idx - ci * 324;
        int ii = rem / 18, jj = rem - (rem / 18) * 18;
        float v = 0.f;
        if (ii >= 1 && ii <= 16 && jj >= 1 && jj <= 16)
            v = Xb[(size_t)ci * 65536 + (ii - 1) * 256 + (jj - 1)];
        sh_in[ci][ii][jj] = v;
    }
    __syncthreads();

    int i = t >> 4, j = t & 15;
    float in_reg[3][9];
    #pragma unroll
    for (int ci = 0; ci < 3; ci++)
        #pragma unroll
        for (int dy = 0; dy < 3; dy++)
            #pragma unroll
            for (int dx = 0; dx < 3; dx++)
                in_reg[ci][dy * 3 + dx] = sh_in[ci][i + dy][j + dx];

    float y[8];
    #pragma unroll
    for (int co = 0; co < 8; co++) {
        float acc = sh_b[co];
        #pragma unroll
        for (int ci = 0; ci < 3; ci++)
            #pragma unroll
            for (int k = 0; k < 9; k++)
                acc += sh_w[co * 27 + ci * 9 + k] * in_reg[ci][k];
        y[co] = fmaxf(acc, 0.f);
    }

    #pragma unroll
    for (int co = 0; co < 8; co++) {
        float v = y[co];
        #pragma unroll
        for (int off = 16; off; off >>= 1)
            v += __shfl_down_sync(0xffffffffu, v, off);
        if ((t & 31) == 0) sh_ws[t >> 5][co] = v;
    }
    __syncthreads();
    if (t < 8) {
        float tot = 0.f;
        #pragma unroll
        for (int w = 0; w < 8; w++) tot += sh_ws[w][t];
        int py = r >> 1, px = c >> 1;
        atomicAdd(&g_feat[b * 512 + t * 64 + py * 8 + px], tot * gate * (1.f / 1024.f));
    }
}

// ---------------------------------------------------------------------------
// Kernel 5: classifier GEMM [16,512]x[512,1000] + bias, plus aux loss.
// grid (8 j-tiles, 16 batch), 128 threads.
// ---------------------------------------------------------------------------
__global__ void __launch_bounds__(128) linear_kernel(const float* __restrict__ lw,
                                                     const float* __restrict__ lb,
                                                     float* __restrict__ out,
                                                     int out_size) {
    __shared__ float fs[512];
    int bx = blockIdx.x, by = blockIdx.y;
    int t = threadIdx.x;
    for (int k = t; k < 512; k += 128) fs[k] = g_feat[by * 512 + k];
    __syncthreads();

    int j = bx * 128 + t;
    if (j < 1000) {
        float acc = 0.f;
        #pragma unroll 8
        for (int k = 0; k < 512; k++)
            acc += fs[k] * lw[(size_t)k * 1000 + j];
        out[by * 1000 + j] = acc + lb[j];
    }
    if (bx == 0 && by == 0 && t == 0) {
        float aux = 0.f;
        #pragma unroll
        for (int e = 0; e < NE; e++) {
            float f = fminf((float)g_cnt[e], (float)CCAP) * (1.f / (float)NTOK);
            aux += f * (g_psum[e] * (1.f / (float)NTOK));
        }
        out[out_size - 1] = 8.f * aux;
    }
}

// ---------------------------------------------------------------------------
extern "C" void kernel_launch(void* const* d_in, const int* in_sizes, int n_in,
                              void* d_out, int out_size) {
    const float* X  = (const float*)d_in[0];
    const float* ew = (const float*)d_in[1];
    const float* eb = (const float*)d_in[2];
    const float* gw = (const float*)d_in[3];
    const float* gb = (const float*)d_in[4];
    const float* lw = (const float*)d_in[5];
    const float* lb = (const float*)d_in[6];
    float* out = (float*)d_out;

    init_kernel<<<33, 256>>>(gw, gb);
    gate_kernel<<<NTOK / 8, 256>>>(X, gw);
    rank_kernel<<<1, 256>>>();
    conv_kernel<<<NTOK, 256>>>(X, ew, eb);
    dim3 g(8, 16);
    linear_kernel<<<g, 128>>>(lw, lb, out, out_size);
}

// round 3
// speedup vs baseline: 1.5607x; 1.5390x over previous
#include <cuda_runtime.h>

// Problem constants
#define BB    16
#define CIN   3
#define HIMG  256
#define PSZ   16
#define HP    16      // patches per side
#define PPI   256     // patches per image
#define NTOK  4096    // total patches
#define NE    8
#define CCAP  640
#define NCOUT 8

// Scratch (device globals; no allocation allowed)
__device__ float g_gate_pos[PPI * NE];
__device__ int   g_eidx[NTOK];
__device__ float g_gate[NTOK];
__device__ float g_psum[NE];
__device__ int   g_cnt[NE];
__device__ float g_feat[BB * 512];

// ---------------------------------------------------------------------------
// Kernel 1: init — block 0 computes gate_pos table + zeroes psum;
//           blocks 1..32 zero g_feat.
// ---------------------------------------------------------------------------
__global__ void init_kernel(const float* __restrict__ gate_w,
                            const float* __restrict__ gate_b) {
    int bid = blockIdx.x;
    int t = threadIdx.x;
    if (bid == 0) {
        if (t < NE) g_psum[t] = 0.f;
        int p = t;
        int r = p >> 4, c = p & 15;
        const float PI2 = 6.283185307179586f;
        float sgx = 0.f, s0x = 0.f, c0x = 0.f, s1x = 0.f, c1x = 0.f;
        for (int j = 0; j < 16; j++) {
            float gx = (float)(c * 16 + j) * (1.0f / 256.0f);
            sgx += gx;
            float a = PI2 * gx;
            s0x += sinf(a);        c0x += cosf(a);
            s1x += sinf(2.f * a);  c1x += cosf(2.f * a);
        }
        float sgy = 0.f, s0y = 0.f, c0y = 0.f, s1y = 0.f, c1y = 0.f;
        for (int i = 0; i < 16; i++) {
            float gy = (float)(r * 16 + i) * (1.0f / 256.0f);
            sgy += gy;
            float a = PI2 * gy;
            s0y += sinf(a);        c0y += cosf(a);
            s1y += sinf(2.f * a);  c1y += cosf(2.f * a);
        }
        float pcx = (c + 0.5f) / 16.f, pcy = (r + 0.5f) / 16.f;
        float S[20];
        S[0]  = 16.f * sgx;              S[1]  = 16.f * sgy;
        S[2]  = 256.f * pcx;             S[3]  = 256.f * pcy;
        S[4]  = 16.f * s0x;              S[5]  = 16.f * c0x;
        S[6]  = 16.f * s0y;              S[7]  = 16.f * c0y;
        S[8]  = 256.f * sinf(PI2 * pcx); S[9]  = 256.f * cosf(PI2 * pcx);
        S[10] = 256.f * sinf(PI2 * pcy); S[11] = 256.f * cosf(PI2 * pcy);
        S[12] = 16.f * s1x;              S[13] = 16.f * c1x;
        S[14] = 16.f * s1y;              S[15] = 16.f * c1y;
        S[16] = 256.f * sinf(2.f * PI2 * pcx); S[17] = 256.f * cosf(2.f * PI2 * pcx);
        S[18] = 256.f * sinf(2.f * PI2 * pcy); S[19] = 256.f * cosf(2.f * PI2 * pcy);
        #pragma unroll
        for (int e = 0; e < NE; e++) {
            float acc = 0.f;
            #pragma unroll
            for (int cc = 0; cc < 20; cc++)
                acc += S[cc] * gate_w[e * 23 + 3 + cc];
            g_gate_pos[p * NE + e] = acc * (1.f / 256.f) + gate_b[e];
        }
    } else {
        int idx = (bid - 1) * 256 + t;
        if (idx < BB * 512) g_feat[idx] = 0.f;
    }
}

// ---------------------------------------------------------------------------
// Kernel 2: gating — one warp per patch.
// ---------------------------------------------------------------------------
__global__ void __launch_bounds__(256) gate_kernel(const float* __restrict__ X,
                                                   const float* __restrict__ gate_w) {
    __shared__ float s_psum[NE];
    int t = threadIdx.x;
    if (t < NE) s_psum[t] = 0.f;
    __syncthreads();

    int warp = t >> 5, lane = t & 31;
    int n = blockIdx.x * 8 + warp;
    int b = n >> 8, p = n & 255;
    int r = p >> 4, c = p & 15;

    float s[3];
    #pragma unroll
    for (int ch = 0; ch < 3; ch++) {
        const float* base = X + ((size_t)(b * 3 + ch) * 256 + r * 16) * 256 + c * 16;
        float acc = 0.f;
        #pragma unroll
        for (int it = 0; it < 2; it++) {
            float4 v = *(const float4*)(base + (size_t)((lane >> 2) + it * 8) * 256 + (lane & 3) * 4);
            acc += v.x + v.y + v.z + v.w;
        }
        #pragma unroll
        for (int off = 16; off; off >>= 1)
            acc += __shfl_down_sync(0xffffffffu, acc, off);
        s[ch] = __shfl_sync(0xffffffffu, acc, 0);
    }

    float lg = -1e30f;
    if (lane < NE) {
        lg = (s[0] * gate_w[lane * 23 + 0] + s[1] * gate_w[lane * 23 + 1] +
              s[2] * gate_w[lane * 23 + 2]) * (1.f / 256.f)
             + g_gate_pos[p * NE + lane];
    }
    float m = lg;
    #pragma unroll
    for (int off = 4; off; off >>= 1)
        m = fmaxf(m, __shfl_xor_sync(0xffffffffu, m, off));
    float pe = (lane < NE) ? expf(lg - m) : 0.f;
    float sum = pe;
    #pragma unroll
    for (int off = 4; off; off >>= 1)
        sum += __shfl_xor_sync(0xffffffffu, sum, off);
    if (lane < NE) {
        float prob = pe / sum;
        atomicAdd(&s_psum[lane], prob);
    }
    unsigned mask = __ballot_sync(0xffffffffu, lg == m) & 0xFFu;
    if (lane == 0) {
        g_eidx[n] = __ffs(mask) - 1;
        g_gate[n] = 1.0f / sum;
    }
    __syncthreads();
    if (t < NE) atomicAdd(&g_psum[t], s_psum[t]);
}

// ---------------------------------------------------------------------------
// Kernel 3: ordered rank per expert (capacity drop). 8 warps, 1 block.
// ---------------------------------------------------------------------------
__global__ void rank_kernel() {
    int w = threadIdx.x >> 5, lane = threadIdx.x & 31;
    int base = 0;
    #pragma unroll 4
    for (int tt = 0; tt < NTOK / 32; tt++) {
        int idx = tt * 32 + lane;
        int e = __ldg(&g_eidx[idx]);
        unsigned mask = __ballot_sync(0xffffffffu, e == w);
        if (e == w) {
            int rank = base + __popc(mask & ((1u << lane) - 1u));
            if (rank >= CCAP) g_gate[idx] = 0.f;
        }
        base += __popc(mask);
    }
    if (lane == 0) g_cnt[w] = base;
}

// ---------------------------------------------------------------------------
// Kernel 4: per-patch 3x3 conv + ReLU + per-channel sum, gated accumulate.
// One block (256 threads) per patch. Thread = 2 vertically-adjacent pixels
// x 4 output channels (cog = t>>7 selects co 0-3 or 4-7).
// Weight LDS amortized over 2 FMAs; input held in 36 registers.
// ---------------------------------------------------------------------------
__global__ void __launch_bounds__(256, 4) conv_kernel(const float* __restrict__ X,
                                                      const float* __restrict__ ew,
                                                      const float* __restrict__ eb) {
    __shared__ float sh_in[3][20][24];   // row stride 24: conflict-free warp reads
    __shared__ float sh_w[8][28];        // [co][27 weights + bias at 27]
    __shared__ float s_co[8];

    int n = blockIdx.x;
    float gate = g_gate[n];
    if (gate == 0.f) return;
    int e = g_eidx[n];
    int t = threadIdx.x;
    int b = n >> 8, p = n & 255;
    int r = p >> 4, c = p & 15;

    if (t < 216) { int co = t / 27; sh_w[co][t - co * 27] = ew[e * 216 + t]; }
    if (t >= 216 && t < 224) sh_w[t - 216][27] = eb[e * 8 + (t - 216)];
    if (t >= 224 && t < 232) s_co[t - 224] = 0.f;

    const float* Xb = X + (size_t)b * 3 * 65536 + (size_t)(r * 16) * 256 + c * 16;
    for (int idx = t; idx < 3 * 18 * 18; idx += 256) {
        int ci = idx / 324;
        int rem = idx - ci * 324;
        int ii = rem / 18, jj = rem - ii * 18;
        float v = 0.f;
        if (ii >= 1 && ii <= 16 && jj >= 1 && jj <= 16)
            v = Xb[(size_t)ci * 65536 + (ii - 1) * 256 + (jj - 1)];
        sh_in[ci][ii][jj] = v;
    }
    __syncthreads();

    int q = t & 127;            // pixel-pair id
    int cog = t >> 7;           // co group: 0 -> co 0-3, 1 -> co 4-7
    int prow = q >> 4;          // 0..7 -> pixel rows 2*prow, 2*prow+1
    int col = q & 15;
    int row0 = prow * 2;        // halo rows row0 .. row0+3

    // input window in registers: 3 ci x 4 rows x 3 cols
    float inr[3][4][3];
    #pragma unroll
    for (int ci = 0; ci < 3; ci++)
        #pragma unroll
        for (int k = 0; k < 4; k++)
            #pragma unroll
            for (int dx = 0; dx < 3; dx++)
                inr[ci][k][dx] = sh_in[ci][row0 + k][col + dx];

    float a0[4], a1[4];
    #pragma unroll
    for (int co = 0; co < 4; co++) {
        float bb = sh_w[cog * 4 + co][27];
        a0[co] = bb; a1[co] = bb;
    }
    #pragma unroll
    for (int ci = 0; ci < 3; ci++)
        #pragma unroll
        for (int dy = 0; dy < 3; dy++)
            #pragma unroll
            for (int dx = 0; dx < 3; dx++) {
                float iv0 = inr[ci][dy][dx];
                float iv1 = inr[ci][dy + 1][dx];
                int k = ci * 9 + dy * 3 + dx;
                #pragma unroll
                for (int co = 0; co < 4; co++) {
                    float wv = sh_w[cog * 4 + co][k];
                    a0[co] = fmaf(wv, iv0, a0[co]);
                    a1[co] = fmaf(wv, iv1, a1[co]);
                }
            }

    float v[4];
    #pragma unroll
    for (int co = 0; co < 4; co++)
        v[co] = fmaxf(a0[co], 0.f) + fmaxf(a1[co], 0.f);

    // butterfly: fold co dimension into lane bits 4 and 3, then reduce 8 lanes
    int lane = t & 31;
    float s0, s1, o0, o1;
    if (lane & 16) { s0 = v[2]; s1 = v[3]; o0 = v[0]; o1 = v[1]; }
    else           { s0 = v[0]; s1 = v[1]; o0 = v[2]; o1 = v[3]; }
    s0 += __shfl_xor_sync(0xffffffffu, o0, 16);
    s1 += __shfl_xor_sync(0xffffffffu, o1, 16);
    float s, o;
    if (lane & 8) { s = s1; o = s0; } else { s = s0; o = s1; }
    s += __shfl_xor_sync(0xffffffffu, o, 8);
    s += __shfl_xor_sync(0xffffffffu, s, 4);
    s += __shfl_xor_sync(0xffffffffu, s, 2);
    s += __shfl_xor_sync(0xffffffffu, s, 1);
    // lane holds full-warp sum for co = cog*4 + 2*bit4 + bit3
    if ((lane & 7) == 0) {
        int co = cog * 4 + ((lane >> 4) & 1) * 2 + ((lane >> 3) & 1);
        atomicAdd(&s_co[co], s);
    }
    __syncthreads();
    if (t < 8) {
        int py = r >> 1, px = c >> 1;
        atomicAdd(&g_feat[b * 512 + t * 64 + py * 8 + px],
                  s_co[t] * gate * (1.f / 1024.f));
    }
}

// ---------------------------------------------------------------------------
// Kernel 5: classifier GEMM [16,512]x[512,1000] + bias, plus aux loss.
// ---------------------------------------------------------------------------
__global__ void __launch_bounds__(128) linear_kernel(const float* __restrict__ lw,
                                                     const float* __restrict__ lb,
                                                     float* __restrict__ out,
                                                     int out_size) {
    __shared__ float fs[512];
    int bx = blockIdx.x, by = blockIdx.y;
    int t = threadIdx.x;
    for (int k = t; k < 512; k += 128) fs[k] = g_feat[by * 512 + k];
    __syncthreads();

    int j = bx * 128 + t;
    if (j < 1000) {
        float acc = 0.f;
        #pragma unroll 8
        for (int k = 0; k < 512; k++)
            acc += fs[k] * lw[(size_t)k * 1000 + j];
        out[by * 1000 + j] = acc + lb[j];
    }
    if (bx == 0 && by == 0 && t == 0) {
        float aux = 0.f;
        #pragma unroll
        for (int e = 0; e < NE; e++) {
            float f = fminf((float)g_cnt[e], (float)CCAP) * (1.f / (float)NTOK);
            aux += f * (g_psum[e] * (1.f / (float)NTOK));
        }
        out[out_size - 1] = 8.f * aux;
    }
}

// ---------------------------------------------------------------------------
extern "C" void kernel_launch(void* const* d_in, const int* in_sizes, int n_in,
                              void* d_out, int out_size) {
    const float* X  = (const float*)d_in[0];
    const float* ew = (const float*)d_in[1];
    const float* eb = (const float*)d_in[2];
    const float* gw = (const float*)d_in[3];
    const float* gb = (const float*)d_in[4];
    const float* lw = (const float*)d_in[5];
    const float* lb = (const float*)d_in[6];
    float* out = (float*)d_out;

    init_kernel<<<33, 256>>>(gw, gb);
    gate_kernel<<<NTOK / 8, 256>>>(X, gw);
    rank_kernel<<<1, 256>>>();
    conv_kernel<<<NTOK, 256>>>(X, ew, eb);
    dim3 g(8, 16);
    linear_kernel<<<g, 128>>>(lw, lb, out, out_size);
}

// round 4
// speedup vs baseline: 1.9485x; 1.2485x over previous
#include <cuda_runtime.h>

// Problem constants
#define BB    16
#define NTOK  4096
#define PPI   256
#define NE    8
#define CCAP  640

// Scratch (device globals; no allocation allowed)
__device__ float g_gate_pos[PPI * NE];
__device__ int   g_eidx[NTOK];
__device__ float g_gate[NTOK];        // prob at argmax; zeroed by rank if dropped
__device__ float g_psum[NE];
__device__ int   g_cnt[NE];
__device__ float g_tok[NTOK * NE];    // per-token per-co ReLU sums (ungated)
__device__ float g_feat[BB * 512];

// ---------------------------------------------------------------------------
// Kernel 1: init — gate_pos table + zero psum. One block.
// ---------------------------------------------------------------------------
__global__ void init_kernel(const float* __restrict__ gate_w,
                            const float* __restrict__ gate_b) {
    int t = threadIdx.x;
    if (t < NE) g_psum[t] = 0.f;
    int p = t;
    int r = p >> 4, c = p & 15;
    const float PI2 = 6.283185307179586f;
    float sgx = 0.f, s0x = 0.f, c0x = 0.f, s1x = 0.f, c1x = 0.f;
    for (int j = 0; j < 16; j++) {
        float gx = (float)(c * 16 + j) * (1.0f / 256.0f);
        sgx += gx;
        float a = PI2 * gx;
        s0x += sinf(a);        c0x += cosf(a);
        s1x += sinf(2.f * a);  c1x += cosf(2.f * a);
    }
    float sgy = 0.f, s0y = 0.f, c0y = 0.f, s1y = 0.f, c1y = 0.f;
    for (int i = 0; i < 16; i++) {
        float gy = (float)(r * 16 + i) * (1.0f / 256.0f);
        sgy += gy;
        float a = PI2 * gy;
        s0y += sinf(a);        c0y += cosf(a);
        s1y += sinf(2.f * a);  c1y += cosf(2.f * a);
    }
    float pcx = (c + 0.5f) / 16.f, pcy = (r + 0.5f) / 16.f;
    float S[20];
    S[0]  = 16.f * sgx;              S[1]  = 16.f * sgy;
    S[2]  = 256.f * pcx;             S[3]  = 256.f * pcy;
    S[4]  = 16.f * s0x;              S[5]  = 16.f * c0x;
    S[6]  = 16.f * s0y;              S[7]  = 16.f * c0y;
    S[8]  = 256.f * sinf(PI2 * pcx); S[9]  = 256.f * cosf(PI2 * pcx);
    S[10] = 256.f * sinf(PI2 * pcy); S[11] = 256.f * cosf(PI2 * pcy);
    S[12] = 16.f * s1x;              S[13] = 16.f * c1x;
    S[14] = 16.f * s1y;              S[15] = 16.f * c1y;
    S[16] = 256.f * sinf(2.f * PI2 * pcx); S[17] = 256.f * cosf(2.f * PI2 * pcx);
    S[18] = 256.f * sinf(2.f * PI2 * pcy); S[19] = 256.f * cosf(2.f * PI2 * pcy);
    #pragma unroll
    for (int e = 0; e < NE; e++) {
        float acc = 0.f;
        #pragma unroll
        for (int cc = 0; cc < 20; cc++)
            acc += S[cc] * gate_w[e * 23 + 3 + cc];
        g_gate_pos[p * NE + e] = acc * (1.f / 256.f) + gate_b[e];
    }
}

// ---------------------------------------------------------------------------
// Kernel 2: megaconv — one block (128 thr) per patch.
// Phase A: stage patch into smem (zero-padded halo) + channel sums on the fly.
// Phase B: every warp redundantly computes softmax/argmax -> expert e.
// Phase C: load W[e] transposed [k][co]; 3x3 conv, thread = 2x2 px * 4 co.
// Phase D: ReLU + per-co patch sum -> g_tok (ungated; rank applied later).
// ---------------------------------------------------------------------------
__global__ void __launch_bounds__(128) megaconv_kernel(const float* __restrict__ X,
                                                       const float* __restrict__ ew,
                                                       const float* __restrict__ eb,
                                                       const float* __restrict__ gw) {
    __shared__ __align__(16) float sh_in[1080];   // 3 ci x 18 rows x 20 stride
    __shared__ __align__(16) float sh_wT[216];    // [k][co] transposed
    __shared__ __align__(16) float sh_b[8];
    __shared__ float s_part[4][3];
    __shared__ float s_co[8];

    int n = blockIdx.x;
    int t = threadIdx.x;
    int b = n >> 8, p = n & 255;
    int r = p >> 4, c = p & 15;
    int lane = t & 31, wid = t >> 5;

    // zero halo (whole array) with float4 stores
    #pragma unroll
    for (int k = 0; k < 3; k++) {
        int i = t + k * 128;
        if (i < 270) ((float4*)sh_in)[i] = make_float4(0.f, 0.f, 0.f, 0.f);
    }
    if (t < 8) s_co[t] = 0.f;
    __syncthreads();

    // fill interior + channel partial sums
    const float* Xb = X + (size_t)b * 3 * 65536 + (size_t)(r * 16) * 256 + c * 16;
    int col = t & 15, rw = t >> 4;   // 16 cols x 8 row-slots
    float sc[3] = {0.f, 0.f, 0.f};
    #pragma unroll
    for (int ci = 0; ci < 3; ci++) {
        #pragma unroll
        for (int k = 0; k < 2; k++) {
            int row = rw + k * 8;
            float v = Xb[ci * 65536 + row * 256 + col];
            sh_in[ci * 360 + (row + 1) * 20 + (col + 1)] = v;
            sc[ci] += v;
        }
    }
    #pragma unroll
    for (int ci = 0; ci < 3; ci++) {
        float v = sc[ci];
        #pragma unroll
        for (int off = 16; off; off >>= 1)
            v += __shfl_xor_sync(0xffffffffu, v, off);
        if (lane == 0) s_part[wid][ci] = v;
    }
    __syncthreads();

    // per-warp gating (redundant across warps -> no extra barrier)
    float S0 = s_part[0][0] + s_part[1][0] + s_part[2][0] + s_part[3][0];
    float S1 = s_part[0][1] + s_part[1][1] + s_part[2][1] + s_part[3][1];
    float S2 = s_part[0][2] + s_part[1][2] + s_part[2][2] + s_part[3][2];
    float lg = -1e30f;
    if (lane < NE) {
        lg = (S0 * gw[lane * 23 + 0] + S1 * gw[lane * 23 + 1] +
              S2 * gw[lane * 23 + 2]) * (1.f / 256.f)
             + g_gate_pos[p * NE + lane];
    }
    float m = lg;
    #pragma unroll
    for (int off = 4; off; off >>= 1)
        m = fmaxf(m, __shfl_xor_sync(0xffffffffu, m, off));
    float pe = (lane < NE) ? expf(lg - m) : 0.f;
    float sum = pe;
    #pragma unroll
    for (int off = 4; off; off >>= 1)
        sum += __shfl_xor_sync(0xffffffffu, sum, off);
    unsigned mk = __ballot_sync(0xffffffffu, lg == m) & 0xFFu;
    int e = __ffs(mk) - 1;      // uniform across warp, identical in all warps
    if (wid == 0) {
        if (lane < NE) atomicAdd(&g_psum[lane], pe / sum);
        if (lane == 0) { g_eidx[n] = e; g_gate[n] = 1.0f / sum; }
    }

    // load expert weights transposed: sh_wT[k*8+co]
    #pragma unroll
    for (int k2 = 0; k2 < 2; k2++) {
        int idx = t + k2 * 128;
        if (idx < 216) {
            int co = idx / 27, kk = idx - co * 27;
            sh_wT[kk * 8 + co] = ew[e * 216 + idx];
        }
    }
    if (t < 8) sh_b[t] = eb[e * 8 + t];
    __syncthreads();

    // conv: thread = 2x2 pixel block x 4 output channels
    int cog = t >> 6;            // 0 -> co 0-3, 1 -> co 4-7
    int pb = t & 63;
    int R = (pb >> 3) * 2, C = (pb & 7) * 2;   // padded-array window origin

    float in_f[3][4][4];
    #pragma unroll
    for (int ci = 0; ci < 3; ci++)
        #pragma unroll
        for (int rr = 0; rr < 4; rr++) {
            const float* base = &sh_in[ci * 360 + (R + rr) * 20 + C];
            float2 u0 = *(const float2*)(base);
            float2 u1 = *(const float2*)(base + 2);
            in_f[ci][rr][0] = u0.x; in_f[ci][rr][1] = u0.y;
            in_f[ci][rr][2] = u1.x; in_f[ci][rr][3] = u1.y;
        }

    float4 b4 = ((const float4*)sh_b)[cog];
    float acc[2][2][4];
    #pragma unroll
    for (int py = 0; py < 2; py++)
        #pragma unroll
        for (int px = 0; px < 2; px++) {
            acc[py][px][0] = b4.x; acc[py][px][1] = b4.y;
            acc[py][px][2] = b4.z; acc[py][px][3] = b4.w;
        }

    #pragma unroll
    for (int ci = 0; ci < 3; ci++)
        #pragma unroll
        for (int dy = 0; dy < 3; dy++)
            #pragma unroll
            for (int dx = 0; dx < 3; dx++) {
                int kk = ci * 9 + dy * 3 + dx;
                float4 w4 = ((const float4*)sh_wT)[kk * 2 + cog];
                #pragma unroll
                for (int py = 0; py < 2; py++)
                    #pragma unroll
                    for (int px = 0; px < 2; px++) {
                        float iv = in_f[ci][dy + py][dx + px];
                        acc[py][px][0] = fmaf(w4.x, iv, acc[py][px][0]);
                        acc[py][px][1] = fmaf(w4.y, iv, acc[py][px][1]);
                        acc[py][px][2] = fmaf(w4.z, iv, acc[py][px][2]);
                        acc[py][px][3] = fmaf(w4.w, iv, acc[py][px][3]);
                    }
            }

    float v[4];
    #pragma unroll
    for (int co = 0; co < 4; co++)
        v[co] = fmaxf(acc[0][0][co], 0.f) + fmaxf(acc[0][1][co], 0.f) +
                fmaxf(acc[1][0][co], 0.f) + fmaxf(acc[1][1][co], 0.f);

    // butterfly: fold co into lane bits 4,3, reduce remaining 8 lanes
    float s0, s1, o0, o1;
    if (lane & 16) { s0 = v[2]; s1 = v[3]; o0 = v[0]; o1 = v[1]; }
    else           { s0 = v[0]; s1 = v[1]; o0 = v[2]; o1 = v[3]; }
    s0 += __shfl_xor_sync(0xffffffffu, o0, 16);
    s1 += __shfl_xor_sync(0xffffffffu, o1, 16);
    float s, o;
    if (lane & 8) { s = s1; o = s0; } else { s = s0; o = s1; }
    s += __shfl_xor_sync(0xffffffffu, o, 8);
    s += __shfl_xor_sync(0xffffffffu, s, 4);
    s += __shfl_xor_sync(0xffffffffu, s, 2);
    s += __shfl_xor_sync(0xffffffffu, s, 1);
    if ((lane & 7) == 0) {
        int co = cog * 4 + ((lane >> 4) & 1) * 2 + ((lane >> 3) & 1);
        atomicAdd(&s_co[co], s);
    }
    __syncthreads();
    if (t < 8) g_tok[n * 8 + t] = s_co[t];
}

// ---------------------------------------------------------------------------
// Kernel 3: ordered rank per expert (capacity drop). 1 block, smem-staged.
// ---------------------------------------------------------------------------
__global__ void rank_kernel() {
    __shared__ int se[NTOK];
    int t = threadIdx.x;
    for (int i = t; i < NTOK; i += 256) se[i] = g_eidx[i];
    __syncthreads();
    int w = t >> 5, lane = t & 31;
    int base = 0;
    #pragma unroll 4
    for (int tt = 0; tt < NTOK / 32; tt++) {
        int idx = tt * 32 + lane;
        int e = se[idx];
        unsigned mask = __ballot_sync(0xffffffffu, e == w);
        if (e == w) {
            int rank = base + __popc(mask & ((1u << lane) - 1u));
            if (rank >= CCAP) g_gate[idx] = 0.f;
        }
        base += __popc(mask);
    }
    if (lane == 0) g_cnt[w] = base;
}

// ---------------------------------------------------------------------------
// Kernel 4: combine — g_feat[b, co, py, px] = sum over 2x2 tokens of
// g_tok * gate / 1024. No atomics; writes every element.
// ---------------------------------------------------------------------------
__global__ void __launch_bounds__(512) combine_kernel() {
    int b = blockIdx.x;
    int t = threadIdx.x;       // t = co*64 + py*8 + px
    int co = t >> 6;
    int cell = t & 63;
    int py = cell >> 3, px = cell & 7;
    float acc = 0.f;
    #pragma unroll
    for (int dy = 0; dy < 2; dy++)
        #pragma unroll
        for (int dx = 0; dx < 2; dx++) {
            int n = b * 256 + (2 * py + dy) * 16 + (2 * px + dx);
            acc += g_tok[n * 8 + co] * g_gate[n];
        }
    g_feat[b * 512 + t] = acc * (1.f / 1024.f);
}

// ---------------------------------------------------------------------------
// Kernel 5: classifier GEMM [16,512]x[512,1000] + bias, plus aux loss.
// ---------------------------------------------------------------------------
__global__ void __launch_bounds__(128) linear_kernel(const float* __restrict__ lw,
                                                     const float* __restrict__ lb,
                                                     float* __restrict__ out,
                                                     int out_size) {
    __shared__ float fs[512];
    int bx = blockIdx.x, by = blockIdx.y;
    int t = threadIdx.x;
    for (int k = t; k < 512; k += 128) fs[k] = g_feat[by * 512 + k];
    __syncthreads();

    int j = bx * 128 + t;
    if (j < 1000) {
        float acc = 0.f;
        #pragma unroll 8
        for (int k = 0; k < 512; k++)
            acc += fs[k] * lw[(size_t)k * 1000 + j];
        out[by * 1000 + j] = acc + lb[j];
    }
    if (bx == 0 && by == 0 && t == 0) {
        float aux = 0.f;
        #pragma unroll
        for (int e = 0; e < NE; e++) {
            float f = fminf((float)g_cnt[e], (float)CCAP) * (1.f / (float)NTOK);
            aux += f * (g_psum[e] * (1.f / (float)NTOK));
        }
        out[out_size - 1] = 8.f * aux;
    }
}

// ---------------------------------------------------------------------------
extern "C" void kernel_launch(void* const* d_in, const int* in_sizes, int n_in,
                              void* d_out, int out_size) {
    const float* X  = (const float*)d_in[0];
    const float* ew = (const float*)d_in[1];
    const float* eb = (const float*)d_in[2];
    const float* gw = (const float*)d_in[3];
    const float* gb = (const float*)d_in[4];
    const float* lw = (const float*)d_in[5];
    const float* lb = (const float*)d_in[6];
    float* out = (float*)d_out;

    init_kernel<<<1, 256>>>(gw, gb);
    megaconv_kernel<<<NTOK, 128>>>(X, ew, eb, gw);
    rank_kernel<<<1, 256>>>();
    combine_kernel<<<BB, 512>>>();
    dim3 g(8, 16);
    linear_kernel<<<g, 128>>>(lw, lb, out, out_size);
}